// round 12
// baseline (speedup 1.0000x reference)
#include <cuda_runtime.h>
#include <cuda_fp16.h>
#include <math_constants.h>

#define BATCH     16
#define FRAMES    4000
#define BINS      257
#define HOP       128
#define G         29
#define NGROUPS   138
#define FRAMES_SH 32
#define OUT_LEN   512383

#define SMEM_BYTES (FRAMES_SH * 512 * 2)   // 32768: half frame buffer

// transpose swizzle on half2 slot index p in [0,256)
#define TSWZ(p) ((p) ^ (((p) >> 5) & 7))

__global__ __launch_bounds__(256, 3)
void istft_kernel(const float* __restrict__ xr,
                  const float* __restrict__ xi,
                  float* __restrict__ out)
{
    extern __shared__ __align__(16) char smem_raw[];
    __half* fr = (__half*)smem_raw;

    const int tid   = threadIdx.x;     // 256
    const int warp  = tid >> 5;
    const int lane  = tid & 31;
    const int group = blockIdx.x;
    const int batch = blockIdx.y;
    const int f0     = group * G;
    const int fstart = f0 - 3;

    // ---- per-lane twiddles (frame-invariant) ----
    float pls, plc;   __sincosf(CUDART_PI_F * (float)lane * (1.0f / 256.0f), &pls, &plc);  // prerot base
    float s128, c128; __sincosf(CUDART_PI_F * (float)lane * (1.0f / 128.0f), &s128, &c128);
    float s64,  c64;  __sincosf(CUDART_PI_F * (float)lane * (1.0f / 64.0f),  &s64,  &c64);
    float s32,  c32;  __sincosf(CUDART_PI_F * (float)lane * (1.0f / 32.0f),  &s32,  &c32);
    float s16,  c16;  __sincosf(CUDART_PI_F * (float)(lane & 15) * (1.0f / 16.0f), &s16, &c16);
    float s8t,  c8t;  __sincosf(CUDART_PI_F * (float)(lane & 7)  * (1.0f / 8.0f),  &s8t, &c8t);

    const float R2 = 0.70710678118654752f;
    float w128c[4], w128s[4];
    w128c[0] = c128;               w128s[0] = s128;
    w128c[1] = R2 * (c128 - s128); w128s[1] = R2 * (c128 + s128);
    w128c[2] = -s128;              w128s[2] = c128;
    w128c[3] = -R2 * (c128 + s128); w128s[3] = R2 * (c128 - s128);

    // prerot per-j constants e^{i*pi*j/8}
    const float C8[8] = {1.f, 0.92387953251128674f, 0.70710678118654752f, 0.38268343236508977f,
                         0.f, -0.38268343236508977f, -0.70710678118654752f, -0.92387953251128674f};
    const float S8[8] = {0.f, 0.38268343236508977f, 0.70710678118654752f, 0.92387953251128674f,
                         1.f, 0.92387953251128674f, 0.70710678118654752f, 0.38268343236508977f};

    const int rl = (int)(__brev((unsigned)lane) >> 27);     // rev5(lane)
    const int msrc = (32 - lane) & 31;                      // mirror shuffle source
    const size_t bbase = (size_t)batch * FRAMES;

    // window-in-registers: w(64a + b) = K' - K'*cos(pi*a/4 + theta_b), b = 2rl or 2rl+1
    const float KP = 1.0f / 1536.0f;                        // 0.5 / 768
    float th0s, th0c; __sincosf(CUDART_PI_F * (float)(2 * rl)     * (1.0f / 256.0f), &th0s, &th0c);
    float th1s, th1c; __sincosf(CUDART_PI_F * (float)(2 * rl + 1) * (1.0f / 256.0f), &th1s, &th1c);
    const float Kc0 = KP * th0c, Ks0 = KP * th0s;
    const float Kc1 = KP * th1c, Ks1 = KP * th1s;
    const float CA[8] = {1.f,  R2, 0.f, -R2, -1.f, -R2, 0.f,  R2};
    const float SA[8] = {0.f,  R2, 1.f,  R2, 0.f,  -R2, -1.f, -R2};

    // branch-free constants for lane stages m = 16, 8
    const float sg16 = (lane & 16) ? -1.f : 1.f;
    const float W16c = (lane & 16) ? c16 : 1.f, W16s = (lane & 16) ? s16 : 0.f;
    const float sg8  = (lane & 8)  ? -1.f : 1.f;
    const float W8c  = (lane & 8)  ? c8t : 1.f, W8s  = (lane & 8)  ? s8t : 0.f;

    for (int lf = warp; lf < FRAMES_SH; lf += 8) {
        const int f = fstart + lf;
        __half2* rowh = (__half2*)(fr + lf * 512);   // 256 half2 slots

        if ((unsigned)f >= (unsigned)FRAMES) {
            const __half2 z2 = __float2half2_rn(0.f);
            #pragma unroll
            for (int q = 0; q < 8; q++) rowh[(q << 5) + lane] = z2;
            continue;
        }

        const float* pre = xr + (bbase + f) * BINS;
        const float* pim = xi + (bbase + f) * BINS;

        // ---- load each bin once: k = 32*j + lane (coalesced) ----
        float kr[8], ki[8];
        #pragma unroll
        for (int j = 0; j < 8; j++) {
            int k = 32 * j + lane;
            kr[j] = pre[k];
            ki[j] = pim[k];
        }
        const float pre256 = pre[256];

        float zr[8], zi[8];

        // Hermitian pack + pre-rotation (registers only); mirror via lane shuffle
        #pragma unroll
        for (int j = 0; j < 8; j++) {
            float br = __shfl_sync(0xffffffffu, kr[7 - j], msrc);
            float mi = __shfl_sync(0xffffffffu, ki[7 - j], msrc);
            if (lane == 0) {
                br = (j == 0) ? pre256 : kr[8 - j];
                mi = (j == 0) ? 0.f    : ki[8 - j];
            }
            float ar = kr[j];
            float ai = (j == 0 && lane == 0) ? 0.f : ki[j];
            float er = ar + br, ei = ai - mi;    // bi = -mi
            float dr = ar - br, di = ai + mi;
            float pc = plc * C8[j] - pls * S8[j];
            float ps = plc * S8[j] + pls * C8[j];
            zr[j] = fmaf(-di, pc, fmaf(-dr, ps, er));
            zi[j] = fmaf(-di, ps, fmaf( dr, pc, ei));
        }

        // ---- register stages (h = 128, 64, 32) ----
        #pragma unroll
        for (int j = 0; j < 4; j++) {
            float tr = zr[j] - zr[j + 4], ti = zi[j] - zi[j + 4];
            zr[j] += zr[j + 4]; zi[j] += zi[j + 4];
            zr[j + 4] = tr * w128c[j] - ti * w128s[j];
            zi[j + 4] = tr * w128s[j] + ti * w128c[j];
        }
        #define RB(A,B,CC,SS) { float tr=zr[A]-zr[B], ti=zi[A]-zi[B]; \
            zr[A]+=zr[B]; zi[A]+=zi[B]; zr[B]=tr*(CC)-ti*(SS); zi[B]=tr*(SS)+ti*(CC); }
        RB(0, 2, c64, s64)  RB(4, 6, c64, s64)
        RB(1, 3, -s64, c64) RB(5, 7, -s64, c64)
        RB(0, 1, c32, s32) RB(2, 3, c32, s32)
        RB(4, 5, c32, s32) RB(6, 7, c32, s32)
        #undef RB

        // ---- lane stages (branch-free): m = 16, 8 ----
        #define LSTAGE(MASK, SG, WC, WS)                                        \
        {                                                                       \
            _Pragma("unroll")                                                   \
            for (int j = 0; j < 8; j++) {                                       \
                float orr = __shfl_xor_sync(0xffffffffu, zr[j], (MASK));        \
                float oii = __shfl_xor_sync(0xffffffffu, zi[j], (MASK));        \
                float tr = fmaf(zr[j], (SG), orr);                              \
                float ti = fmaf(zi[j], (SG), oii);                              \
                zr[j] = tr * (WC) - ti * (WS);                                  \
                zi[j] = tr * (WS) + ti * (WC);                                  \
            }                                                                   \
        }
        LSTAGE(16, sg16, W16c, W16s)
        LSTAGE(8,  sg8,  W8c,  W8s)
        #undef LSTAGE

        // ---- warp transpose through the frame's own row (half2, swizzled) ----
        #pragma unroll
        for (int j = 0; j < 8; j++) {
            int p = 32 * j + lane;
            rowh[TSWZ(p)] = __floats2half2_rn(zr[j], zi[j]);
        }
        __syncwarp(0xffffffffu);
        float vr[8], vi[8];
        #pragma unroll
        for (int t = 0; t < 8; t++) {
            int p = 8 * lane + t;
            float2 v = __half22float2(rowh[TSWZ(p)]);
            vr[t] = v.x; vi[t] = v.y;
        }
        __syncwarp(0xffffffffu);

        // ---- register stages d = 4, 2, 1 (constant twiddles) ----
        #define RB1(A,B) { float tr=vr[A]-vr[B], ti=vi[A]-vi[B]; \
            vr[A]+=vr[B]; vi[A]+=vi[B]; vr[B]=tr; vi[B]=ti; }
        #define RBI(A,B) { float tr=vr[A]-vr[B], ti=vi[A]-vi[B]; \
            vr[A]+=vr[B]; vi[A]+=vi[B]; vr[B]=-ti; vi[B]=tr; }
        #define RBC(A,B,CC,SS) { float tr=vr[A]-vr[B], ti=vi[A]-vi[B]; \
            vr[A]+=vr[B]; vi[A]+=vi[B]; vr[B]=tr*(CC)-ti*(SS); vi[B]=tr*(SS)+ti*(CC); }
        RB1(0, 4) RBC(1, 5, R2, R2) RBI(2, 6) RBC(3, 7, -R2, R2)
        RB1(0, 2) RBI(1, 3) RB1(4, 6) RBI(5, 7)
        RB1(0, 1) RB1(2, 3) RB1(4, 5) RB1(6, 7)
        #undef RB1
        #undef RBI
        #undef RBC

        // ---- final windowed store (half2, natural order) ----
        {
            const int rev3t[8] = {0, 4, 2, 6, 1, 5, 3, 7};
            #pragma unroll
            for (int t = 0; t < 8; t++) {
                int a = rev3t[t];
                float w0 = fmaf(SA[a], Ks0, fmaf(-CA[a], Kc0, KP));
                float w1 = fmaf(SA[a], Ks1, fmaf(-CA[a], Kc1, KP));
                int n = (a << 5) + rl;
                rowh[n] = __floats2half2_rn(vr[t] * w0, vi[t] * w1);
            }
        }
    }
    __syncthreads();

    // ---- gather overlap-add: 4 samples/thread, uint2 half reads, scalar stores ----
    const int sbase = f0 * HOP;
    const int owned = (group == NGROUPS - 1) ? (OUT_LEN - sbase) : (G * HOP);
    const int n4 = (owned + 3) >> 2;
    float* outb = out + (size_t)batch * OUT_LEN;
    for (int t = tid; t < n4; t += 256) {
        int s0 = 4 * t;
        int qf = s0 >> 7;
        int r4 = (s0 & 127) >> 2;
        float a0 = 0.f, a1 = 0.f, a2 = 0.f, a3 = 0.f;
        #pragma unroll
        for (int d = 0; d < 4; d++) {
            int lf = qf - d + 3;
            if (lf < FRAMES_SH) {
                uint2 raw = *(const uint2*)&fr[lf * 512 + (r4 << 2) + (d << 7)];
                float2 v0 = __half22float2(*(const __half2*)&raw.x);
                float2 v1 = __half22float2(*(const __half2*)&raw.y);
                a0 += v0.x; a1 += v0.y; a2 += v1.x; a3 += v1.y;
            }
        }
        int S = sbase + s0;
        if (S + 3 < OUT_LEN) {
            outb[S] = a0; outb[S + 1] = a1; outb[S + 2] = a2; outb[S + 3] = a3;
        } else {
            if (S     < OUT_LEN) outb[S]     = a0;
            if (S + 1 < OUT_LEN) outb[S + 1] = a1;
            if (S + 2 < OUT_LEN) outb[S + 2] = a2;
        }
    }
}

extern "C" void kernel_launch(void* const* d_in, const int* in_sizes, int n_in,
                              void* d_out, int out_size)
{
    const float* stft_real = (const float*)d_in[0];
    const float* stft_imag = (const float*)d_in[1];
    float* out = (float*)d_out;
    (void)in_sizes; (void)n_in; (void)out_size;

    cudaFuncSetAttribute(istft_kernel,
                         cudaFuncAttributeMaxDynamicSharedMemorySize, SMEM_BYTES);
    dim3 grid(NGROUPS, BATCH);
    istft_kernel<<<grid, 256, SMEM_BYTES>>>(stft_real, stft_imag, out);
}

// round 13
// speedup vs baseline: 1.0417x; 1.0417x over previous
#include <cuda_runtime.h>
#include <math_constants.h>

#define BATCH     16
#define FRAMES    4000
#define BINS      257
#define HOP       128
#define G         29
#define NGROUPS   138
#define FRAMES_SH 32
#define OUT_LEN   512383

#define SMEM_BYTES (FRAMES_SH * 512 * 4)   // 65536: fp32 frame buffer

typedef unsigned long long u64;
__device__ __forceinline__ u64 pk2(float a, float b) {
    u64 r; asm("mov.b64 %0, {%1,%2};" : "=l"(r) : "f"(a), "f"(b)); return r;
}
__device__ __forceinline__ float2 up2(u64 v) {
    float2 f; asm("mov.b64 {%0,%1}, %2;" : "=f"(f.x), "=f"(f.y) : "l"(v)); return f;
}
__device__ __forceinline__ u64 add2(u64 a, u64 b) {
    u64 r; asm("add.rn.f32x2 %0,%1,%2;" : "=l"(r) : "l"(a), "l"(b)); return r;
}

__global__ __launch_bounds__(256, 3)
void istft_kernel(const float* __restrict__ xr,
                  const float* __restrict__ xi,
                  float* __restrict__ out)
{
    extern __shared__ __align__(16) char smem_raw[];
    float* fr = (float*)smem_raw;

    const int tid   = threadIdx.x;     // 256
    const int warp  = tid >> 5;
    const int lane  = tid & 31;
    const int group = blockIdx.x;
    const int batch = blockIdx.y;
    const int f0     = group * G;
    const int fstart = f0 - 3;

    // ---- per-lane twiddles (frame-invariant) ----
    float pls, plc;   __sincosf(CUDART_PI_F * (float)lane * (1.0f / 256.0f), &pls, &plc);  // prerot base
    float s128, c128; __sincosf(CUDART_PI_F * (float)lane * (1.0f / 128.0f), &s128, &c128);
    float s64,  c64;  __sincosf(CUDART_PI_F * (float)lane * (1.0f / 64.0f),  &s64,  &c64);
    float s32,  c32;  __sincosf(CUDART_PI_F * (float)lane * (1.0f / 32.0f),  &s32,  &c32);
    float s16,  c16;  __sincosf(CUDART_PI_F * (float)(lane & 15) * (1.0f / 16.0f), &s16, &c16);
    float s8t,  c8t;  __sincosf(CUDART_PI_F * (float)(lane & 7)  * (1.0f / 8.0f),  &s8t, &c8t);

    const float R2 = 0.70710678118654752f;
    float w128c[4], w128s[4];
    w128c[0] = c128;               w128s[0] = s128;
    w128c[1] = R2 * (c128 - s128); w128s[1] = R2 * (c128 + s128);
    w128c[2] = -s128;              w128s[2] = c128;
    w128c[3] = -R2 * (c128 + s128); w128s[3] = R2 * (c128 - s128);

    // prerot per-j constants e^{i*pi*j/8}
    const float C8[8] = {1.f, 0.92387953251128674f, 0.70710678118654752f, 0.38268343236508977f,
                         0.f, -0.38268343236508977f, -0.70710678118654752f, -0.92387953251128674f};
    const float S8[8] = {0.f, 0.38268343236508977f, 0.70710678118654752f, 0.92387953251128674f,
                         1.f, 0.92387953251128674f, 0.70710678118654752f, 0.38268343236508977f};

    const int rl = (int)(__brev((unsigned)lane) >> 27);     // rev5(lane)
    const int msrc = (32 - lane) & 31;                      // mirror shuffle source
    const int wx = (lane >> 4) & 1;                         // transpose write xor (low bit)
    const int rx = (lane >> 1) & 15;                        // transpose read xor
    const size_t bbase = (size_t)batch * FRAMES;

    // window-in-registers: w(64a + b) = K' - K'*cos(pi*a/4 + theta_b), b = 2rl or 2rl+1
    const float KP = 1.0f / 1536.0f;                        // 0.5 / 768
    float th0s, th0c; __sincosf(CUDART_PI_F * (float)(2 * rl)     * (1.0f / 256.0f), &th0s, &th0c);
    float th1s, th1c; __sincosf(CUDART_PI_F * (float)(2 * rl + 1) * (1.0f / 256.0f), &th1s, &th1c);
    const float Kc0 = KP * th0c, Ks0 = KP * th0s;
    const float Kc1 = KP * th1c, Ks1 = KP * th1s;
    const float CA[8] = {1.f,  R2, 0.f, -R2, -1.f, -R2, 0.f,  R2};
    const float SA[8] = {0.f,  R2, 1.f,  R2, 0.f,  -R2, -1.f, -R2};

    // branch-free constants for lane stages m = 16, 8
    const float sg16 = (lane & 16) ? -1.f : 1.f;
    const float W16c = (lane & 16) ? c16 : 1.f, W16s = (lane & 16) ? s16 : 0.f;
    const float sg8  = (lane & 8)  ? -1.f : 1.f;
    const float W8c  = (lane & 8)  ? c8t : 1.f, W8s  = (lane & 8)  ? s8t : 0.f;

    for (int lf = warp; lf < FRAMES_SH; lf += 8) {
        const int f = fstart + lf;
        float2* row2 = (float2*)(fr + lf * 512);

        if ((unsigned)f >= (unsigned)FRAMES) {
            #pragma unroll
            for (int q = 0; q < 8; q++) row2[(q << 5) + lane] = make_float2(0.f, 0.f);
            continue;
        }

        const float* pre = xr + (bbase + f) * BINS;
        const float* pim = xi + (bbase + f) * BINS;

        // ---- load each bin once: k = 32*j + lane (coalesced) ----
        float kr[8], ki[8];
        #pragma unroll
        for (int j = 0; j < 8; j++) {
            int k = 32 * j + lane;
            kr[j] = pre[k];
            ki[j] = pim[k];
        }
        const float pre256 = pre[256];

        float zr[8], zi[8];

        // Hermitian pack + pre-rotation (registers only); mirror via lane shuffle
        #pragma unroll
        for (int j = 0; j < 8; j++) {
            float br = __shfl_sync(0xffffffffu, kr[7 - j], msrc);
            float mi = __shfl_sync(0xffffffffu, ki[7 - j], msrc);
            if (lane == 0) {
                br = (j == 0) ? pre256 : kr[8 - j];
                mi = (j == 0) ? 0.f    : ki[8 - j];
            }
            float ar = kr[j];
            float ai = (j == 0 && lane == 0) ? 0.f : ki[j];
            float er = ar + br, ei = ai - mi;    // bi = -mi
            float dr = ar - br, di = ai + mi;
            float pc = plc * C8[j] - pls * S8[j];
            float ps = plc * S8[j] + pls * C8[j];
            zr[j] = fmaf(-di, pc, fmaf(-dr, ps, er));
            zi[j] = fmaf(-di, ps, fmaf( dr, pc, ei));
        }

        // ---- register stages (h = 128, 64, 32) ----
        #pragma unroll
        for (int j = 0; j < 4; j++) {
            float tr = zr[j] - zr[j + 4], ti = zi[j] - zi[j + 4];
            zr[j] += zr[j + 4]; zi[j] += zi[j + 4];
            zr[j + 4] = tr * w128c[j] - ti * w128s[j];
            zi[j + 4] = tr * w128s[j] + ti * w128c[j];
        }
        #define RB(A,B,CC,SS) { float tr=zr[A]-zr[B], ti=zi[A]-zi[B]; \
            zr[A]+=zr[B]; zi[A]+=zi[B]; zr[B]=tr*(CC)-ti*(SS); zi[B]=tr*(SS)+ti*(CC); }
        RB(0, 2, c64, s64)  RB(4, 6, c64, s64)
        RB(1, 3, -s64, c64) RB(5, 7, -s64, c64)
        RB(0, 1, c32, s32) RB(2, 3, c32, s32)
        RB(4, 5, c32, s32) RB(6, 7, c32, s32)
        #undef RB

        // ---- lane stages (branch-free): m = 16, 8 ----
        #define LSTAGE(MASK, SG, WC, WS)                                        \
        {                                                                       \
            _Pragma("unroll")                                                   \
            for (int j = 0; j < 8; j++) {                                       \
                float orr = __shfl_xor_sync(0xffffffffu, zr[j], (MASK));        \
                float oii = __shfl_xor_sync(0xffffffffu, zi[j], (MASK));        \
                float tr = fmaf(zr[j], (SG), orr);                              \
                float ti = fmaf(zi[j], (SG), oii);                              \
                zr[j] = tr * (WC) - ti * (WS);                                  \
                zi[j] = tr * (WS) + ti * (WC);                                  \
            }                                                                   \
        }
        LSTAGE(16, sg16, W16c, W16s)
        LSTAGE(8,  sg8,  W8c,  W8s)
        #undef LSTAGE

        // ---- warp transpose through the frame's own row (swizzled) ----
        #pragma unroll
        for (int j = 0; j < 8; j++) {
            int a = (32 * j + lane) ^ ((j << 1) | wx);
            row2[a] = make_float2(zr[j], zi[j]);
        }
        __syncwarp(0xffffffffu);
        float vr[8], vi[8];
        #pragma unroll
        for (int t = 0; t < 8; t++) {
            float2 v = row2[(8 * lane + t) ^ rx];
            vr[t] = v.x; vi[t] = v.y;
        }
        __syncwarp(0xffffffffu);

        // ---- register stages d = 4, 2, 1 (constant twiddles) ----
        #define RB1(A,B) { float tr=vr[A]-vr[B], ti=vi[A]-vi[B]; \
            vr[A]+=vr[B]; vi[A]+=vi[B]; vr[B]=tr; vi[B]=ti; }
        #define RBI(A,B) { float tr=vr[A]-vr[B], ti=vi[A]-vi[B]; \
            vr[A]+=vr[B]; vi[A]+=vi[B]; vr[B]=-ti; vi[B]=tr; }
        #define RBC(A,B,CC,SS) { float tr=vr[A]-vr[B], ti=vi[A]-vi[B]; \
            vr[A]+=vr[B]; vi[A]+=vi[B]; vr[B]=tr*(CC)-ti*(SS); vi[B]=tr*(SS)+ti*(CC); }
        RB1(0, 4) RBC(1, 5, R2, R2) RBI(2, 6) RBC(3, 7, -R2, R2)
        RB1(0, 2) RBI(1, 3) RB1(4, 6) RBI(5, 7)
        RB1(0, 1) RB1(2, 3) RB1(4, 5) RB1(6, 7)
        #undef RB1
        #undef RBI
        #undef RBC

        // ---- final windowed store, natural order; window from registers ----
        {
            const int rev3t[8] = {0, 4, 2, 6, 1, 5, 3, 7};
            #pragma unroll
            for (int t = 0; t < 8; t++) {
                int a = rev3t[t];
                float w0 = fmaf(SA[a], Ks0, fmaf(-CA[a], Kc0, KP));
                float w1 = fmaf(SA[a], Ks1, fmaf(-CA[a], Kc1, KP));
                int n = (a << 5) + rl;
                row2[n] = make_float2(vr[t] * w0, vi[t] * w1);
            }
        }
    }
    __syncthreads();

    // ---- gather overlap-add ----
    const int sbase = f0 * HOP;
    float* outb = out + (size_t)batch * OUT_LEN;

    if (group != NGROUPS - 1) {
        // branch-free: qf <= 28 -> lf = qf+3-d in [0,31] always valid;
        // sbase + 3712 <= 508544 < OUT_LEN, no store bounds needed.
        // addr(d) = (qf+3)*512 + r - 384*d ; t += 256 => addr += 4096, S += 1024
        int s0 = 4 * tid;
        const float* p = fr + ((s0 >> 7) + 3) * 512 + (s0 & 127);
        float* po = outb + sbase + s0;
        #pragma unroll 2
        for (; s0 < G * HOP; s0 += 1024, p += 4096, po += 1024) {
            float4 v0 = *(const float4*)(p);
            float4 v1 = *(const float4*)(p - 384);
            float4 v2 = *(const float4*)(p - 768);
            float4 v3 = *(const float4*)(p - 1152);
            u64 a = add2(add2(pk2(v0.x, v0.y), pk2(v1.x, v1.y)),
                         add2(pk2(v2.x, v2.y), pk2(v3.x, v3.y)));
            u64 b = add2(add2(pk2(v0.z, v0.w), pk2(v1.z, v1.w)),
                         add2(pk2(v2.z, v2.w), pk2(v3.z, v3.w)));
            float2 fa = up2(a), fb = up2(b);
            po[0] = fa.x; po[1] = fa.y; po[2] = fb.x; po[3] = fb.y;
        }
    } else {
        // tail group: checked path
        const int owned = OUT_LEN - sbase;
        const int n4 = (owned + 3) >> 2;
        for (int t = tid; t < n4; t += 256) {
            int s0 = 4 * t;
            int qf = s0 >> 7;
            int r4 = (s0 & 127) >> 2;
            float a0 = 0.f, a1 = 0.f, a2 = 0.f, a3 = 0.f;
            #pragma unroll
            for (int d = 0; d < 4; d++) {
                int lf = qf - d + 3;
                if (lf < FRAMES_SH) {
                    float4 v = *(const float4*)&fr[lf * 512 + 4 * (r4 + (d << 5))];
                    a0 += v.x; a1 += v.y; a2 += v.z; a3 += v.w;
                }
            }
            int S = sbase + s0;
            if (S + 3 < OUT_LEN) {
                outb[S] = a0; outb[S + 1] = a1; outb[S + 2] = a2; outb[S + 3] = a3;
            } else {
                if (S     < OUT_LEN) outb[S]     = a0;
                if (S + 1 < OUT_LEN) outb[S + 1] = a1;
                if (S + 2 < OUT_LEN) outb[S + 2] = a2;
            }
        }
    }
}

extern "C" void kernel_launch(void* const* d_in, const int* in_sizes, int n_in,
                              void* d_out, int out_size)
{
    const float* stft_real = (const float*)d_in[0];
    const float* stft_imag = (const float*)d_in[1];
    float* out = (float*)d_out;
    (void)in_sizes; (void)n_in; (void)out_size;

    cudaFuncSetAttribute(istft_kernel,
                         cudaFuncAttributeMaxDynamicSharedMemorySize, SMEM_BYTES);
    dim3 grid(NGROUPS, BATCH);
    istft_kernel<<<grid, 256, SMEM_BYTES>>>(stft_real, stft_imag, out);
}